// round 11
// baseline (speedup 1.0000x reference)
#include <cuda_runtime.h>
#include <cuda_fp16.h>

#define N_NODES 100000
#define N_EDGES 1600000
#define F 64
#define NTILES ((N_NODES + 1023) / 1024)   // 98
#define MTILES ((N_NODES + 63) / 64)       // 1563
#define HB 1563                            // hist blocks (400000/256 rounded up)
#define CB 1563                            // conv blocks (400000 threads, 16 floats each)
#define WB 64                              // wprep blocks (16384/256)

typedef unsigned long long ull;

// ---------------- scratch (static device globals; no allocation) ----------------
__device__ int    g_deg[N_NODES];
__device__ int    g_cursor[N_NODES];
__device__ int    g_row_ptr[N_NODES + 1];
__device__ int    g_csr_src[N_EDGES];
__device__ int    g_tile_sum[NTILES];
__device__ int    g_tile_off[NTILES];
__device__ __half g_xh[(size_t)N_NODES * 64];     // fp16 x
__device__ __half g_mh1[(size_t)N_NODES * 64];    // fp16 mean1
__device__ __half g_cat2[(size_t)N_NODES * 128];  // [mean2 | h1] fp16, row 128
__device__ __half g_w1[64 * 128];                 // [W1l | W1r] fp16, row-major j,k
__device__ __half g_w2[64 * 128];
__device__ float  g_sa[N_NODES];
__device__ float  g_sb[N_NODES];

// ---------------- pre: hist atomics + x->fp16 conv + weight pack, one launch ----------------
// Block-range dispatch: streaming conv/wprep blocks keep SMs busy while hist
// ATOMGs drain (hist is latency-bound, issue ~1.6%).
__global__ void pre_kernel(const int* __restrict__ ei, const float* __restrict__ x,
                           const float* __restrict__ W1l, const float* __restrict__ W1r,
                           const float* __restrict__ W2l, const float* __restrict__ W2r)
{
    int b = blockIdx.x, t = threadIdx.x;
    if (b < HB) {
        int e4 = b * 256 + t;
        if (e4 >= N_EDGES / 4) return;
        int4 d = __ldg((const int4*)(ei + N_EDGES) + e4);
        atomicAdd(&g_deg[d.x], 1);
        atomicAdd(&g_deg[d.y], 1);
        atomicAdd(&g_deg[d.z], 1);
        atomicAdd(&g_deg[d.w], 1);
    } else if (b < HB + CB) {
        int i = (b - HB) * 256 + t;            // 400000 threads, 16 floats each
        if (i >= N_NODES * F / 16) return;
        const float4* src = (const float4*)x + (size_t)i * 4;
        uint4 o0, o1;
        float4 v0 = __ldg(src);     float4 v1 = __ldg(src + 1);
        float4 v2 = __ldg(src + 2); float4 v3 = __ldg(src + 3);
        __half2 h;
        h = __floats2half2_rn(v0.x, v0.y); o0.x = *(unsigned*)&h;
        h = __floats2half2_rn(v0.z, v0.w); o0.y = *(unsigned*)&h;
        h = __floats2half2_rn(v1.x, v1.y); o0.z = *(unsigned*)&h;
        h = __floats2half2_rn(v1.z, v1.w); o0.w = *(unsigned*)&h;
        h = __floats2half2_rn(v2.x, v2.y); o1.x = *(unsigned*)&h;
        h = __floats2half2_rn(v2.z, v2.w); o1.y = *(unsigned*)&h;
        h = __floats2half2_rn(v3.x, v3.y); o1.z = *(unsigned*)&h;
        h = __floats2half2_rn(v3.z, v3.w); o1.w = *(unsigned*)&h;
        ((uint4*)g_xh)[(size_t)i * 2]     = o0;
        ((uint4*)g_xh)[(size_t)i * 2 + 1] = o1;
    } else {
        int i = (b - HB - CB) * 256 + t;       // 0..16383
        if (i >= 2 * 64 * 128) return;
        int sel = i >> 13;
        int r = i & 8191;
        int j = r >> 7, k = r & 127;
        const float* Wl = sel ? W2l : W1l;
        const float* Wr = sel ? W2r : W1r;
        float v = (k < 64) ? Wl[j * 64 + k] : Wr[j * 64 + (k - 64)];
        (sel ? g_w2 : g_w1)[r] = __float2half_rn(v);
    }
}

// ---------------- scans ----------------
__global__ void scanA_kernel() {
    __shared__ int wsum[32];
    int t = threadIdx.x, b = blockIdx.x;
    int i = b * 1024 + t;
    int v = (i < N_NODES) ? g_deg[i] : 0;
#pragma unroll
    for (int off = 16; off; off >>= 1)
        v += __shfl_down_sync(0xFFFFFFFFu, v, off);
    if ((t & 31) == 0) wsum[t >> 5] = v;
    __syncthreads();
    if (t < 32) {
        int s = wsum[t];
#pragma unroll
        for (int off = 16; off; off >>= 1)
            s += __shfl_down_sync(0xFFFFFFFFu, s, off);
        if (t == 0) g_tile_sum[b] = s;
    }
}

__global__ void scanB_kernel() {
    __shared__ int sh[NTILES];
    int t = threadIdx.x;
    if (t < NTILES) sh[t] = g_tile_sum[t];
    __syncthreads();
    if (t == 0) {
        int run = 0;
        for (int i = 0; i < NTILES; i++) { int v = sh[i]; sh[i] = run; run += v; }
        g_row_ptr[N_NODES] = run;
    }
    __syncthreads();
    if (t < NTILES) g_tile_off[t] = sh[t];
}

__global__ void scanC_kernel() {
    __shared__ int wsum[32];
    int t = threadIdx.x, b = blockIdx.x;
    int i = b * 1024 + t;
    int v = (i < N_NODES) ? g_deg[i] : 0;
    int lane = t & 31, w = t >> 5;
    int x = v;
#pragma unroll
    for (int off = 1; off < 32; off <<= 1) {
        int y = __shfl_up_sync(0xFFFFFFFFu, x, off);
        if (lane >= off) x += y;
    }
    if (lane == 31) wsum[w] = x;
    __syncthreads();
    if (t < 32) {
        int s = wsum[t];
#pragma unroll
        for (int off = 1; off < 32; off <<= 1) {
            int y = __shfl_up_sync(0xFFFFFFFFu, s, off);
            if (t >= off) s += y;
        }
        wsum[t] = s;
    }
    __syncthreads();
    int base = g_tile_off[b] + (w ? wsum[w - 1] : 0);
    int excl = base + x - v;
    if (i < N_NODES) { g_row_ptr[i] = excl; g_cursor[i] = excl; }
}

__global__ void fill_kernel(const int* __restrict__ ei) {
    int e4 = blockIdx.x * blockDim.x + threadIdx.x;
    if (e4 >= N_EDGES / 4) return;
    int4 s = __ldg((const int4*)ei + e4);
    int4 d = __ldg((const int4*)(ei + N_EDGES) + e4);
    g_csr_src[atomicAdd(&g_cursor[d.x], 1)] = s.x;
    g_csr_src[atomicAdd(&g_cursor[d.y], 1)] = s.y;
    g_csr_src[atomicAdd(&g_cursor[d.z], 1)] = s.z;
    g_csr_src[atomicAdd(&g_cursor[d.w], 1)] = s.w;
}

// ---------------- mean aggregation (fp16 gather, fp32 accumulate) ----------------
// Warp-per-node, 32 lanes x half2 = 128B/edge row. LAYER 0: g_xh -> g_mh1.
// LAYER 1: cat2 right half (h1) -> cat2 left half (mean2).
template<int LAYER>
__global__ void agg_kernel() {
    int warp = (blockIdx.x * blockDim.x + threadIdx.x) >> 5;
    int lane = threadIdx.x & 31;
    if (warp >= N_NODES) return;

    const int beg = g_row_ptr[warp];
    const int end = g_row_ptr[warp + 1];
    const unsigned* __restrict__ xh = (const unsigned*)(LAYER == 0 ? g_xh : g_cat2);
    const int stride = (LAYER == 0) ? 32 : 64;
    const int off    = (LAYER == 0) ? 0  : 32;

    float2 a0 = make_float2(0.f, 0.f), a1 = make_float2(0.f, 0.f);
    float2 a2 = make_float2(0.f, 0.f), a3 = make_float2(0.f, 0.f);

    for (int base = beg; base < end; base += 8) {
        int s[8];
#pragma unroll
        for (int u = 0; u < 8; u++)
            s[u] = (base + u < end) ? __ldg(g_csr_src + base + u) : -1;
        float2 v[8];
#pragma unroll
        for (int u = 0; u < 8; u++) {
            if (s[u] >= 0) {
                unsigned raw = __ldg(xh + (size_t)s[u] * stride + off + lane);
                v[u] = __half22float2(*(__half2*)&raw);
            } else v[u] = make_float2(0.f, 0.f);
        }
        a0.x += v[0].x + v[4].x; a0.y += v[0].y + v[4].y;
        a1.x += v[1].x + v[5].x; a1.y += v[1].y + v[5].y;
        a2.x += v[2].x + v[6].x; a2.y += v[2].y + v[6].y;
        a3.x += v[3].x + v[7].x; a3.y += v[3].y + v[7].y;
    }
    float2 acc;
    acc.x = (a0.x + a1.x) + (a2.x + a3.x);
    acc.y = (a0.y + a1.y) + (a2.y + a3.y);
    float inv = (end > beg) ? 1.0f / (float)(end - beg) : 0.0f;
    __half2 r = __floats2half2_rn(acc.x * inv, acc.y * inv);
    if (LAYER == 0) ((__half2*)g_mh1)[(size_t)warp * 32 + lane] = r;
    else            ((__half2*)g_cat2)[(size_t)warp * 64 + lane] = r;
}

// ---------------- HMMA transform: out = relu([mean|x] @ [Wl|Wr]^T + b) ----------------
// 128 threads, 64-node tile per block. mma.sync.m16n8k16 f16->f32.
// LAYER 0: A = [mh1 | xh], epilogue writes fp16 h1 into cat2 right half.
// LAYER 1: A = cat2 rows, epilogue reduces sa/sb per node (quad shfl, plain stores).
template<int LAYER>
__global__ void __launch_bounds__(128) gemm_kernel(
    const float* __restrict__ bias,
    const float* __restrict__ Wlin)
{
    __shared__ __half smA[64 * 136];   // 272B row stride: conflict-free quads
    const int m0 = blockIdx.x * 64;
    const int tid = threadIdx.x;
    const __half* __restrict__ W = (LAYER == 0) ? g_w1 : g_w2;

    if (LAYER == 0) {
#pragma unroll
        for (int i = 0; i < 4; i++) {   // left: mh1 rows
            int chunk = tid + i * 128;
            int r = chunk >> 3, c = chunk & 7;
            uint4 v = make_uint4(0, 0, 0, 0);
            if (m0 + r < N_NODES) v = *(const uint4*)(g_mh1 + (size_t)(m0 + r) * 64 + c * 8);
            *(uint4*)(smA + r * 136 + c * 8) = v;
        }
#pragma unroll
        for (int i = 0; i < 4; i++) {   // right: xh rows
            int chunk = tid + i * 128;
            int r = chunk >> 3, c = chunk & 7;
            uint4 v = make_uint4(0, 0, 0, 0);
            if (m0 + r < N_NODES) v = *(const uint4*)(g_xh + (size_t)(m0 + r) * 64 + c * 8);
            *(uint4*)(smA + r * 136 + 64 + c * 8) = v;
        }
    } else {
#pragma unroll
        for (int i = 0; i < 8; i++) {
            int chunk = tid + i * 128;
            int r = chunk >> 4, c = chunk & 15;
            uint4 v = make_uint4(0, 0, 0, 0);
            if (m0 + r < N_NODES) v = *(const uint4*)(g_cat2 + (size_t)(m0 + r) * 128 + c * 8);
            *(uint4*)(smA + r * 136 + c * 8) = v;
        }
    }
    __syncthreads();

    const int w = tid >> 5, lane = tid & 31;
    const int qr = lane >> 2, qc = lane & 3;
    const int r0 = w * 16;

    unsigned a[8][4];
#pragma unroll
    for (int k = 0; k < 8; k++) {
        const __half* base = smA + (r0 + qr) * 136 + k * 16 + qc * 2;
        a[k][0] = *(const unsigned*)(base);
        a[k][1] = *(const unsigned*)(base + 8 * 136);
        a[k][2] = *(const unsigned*)(base + 8);
        a[k][3] = *(const unsigned*)(base + 8 * 136 + 8);
    }

    float pa0 = 0.f, pb0 = 0.f, pa1 = 0.f, pb1 = 0.f;

#pragma unroll
    for (int nt = 0; nt < 8; nt++) {
        const int j0 = nt * 8;
        float c0 = 0.f, c1 = 0.f, c2 = 0.f, c3 = 0.f;
#pragma unroll
        for (int k = 0; k < 8; k++) {
            const __half* bb = W + (size_t)(j0 + qr) * 128 + k * 16 + qc * 2;
            unsigned b0 = __ldg((const unsigned*)bb);
            unsigned b1 = __ldg((const unsigned*)(bb + 8));
            asm volatile(
                "mma.sync.aligned.m16n8k16.row.col.f32.f16.f16.f32 "
                "{%0,%1,%2,%3}, {%4,%5,%6,%7}, {%8,%9}, {%0,%1,%2,%3};"
                : "+f"(c0), "+f"(c1), "+f"(c2), "+f"(c3)
                : "r"(a[k][0]), "r"(a[k][1]), "r"(a[k][2]), "r"(a[k][3]),
                  "r"(b0), "r"(b1));
        }
        float2 bj = *(const float2*)(bias + j0 + qc * 2);
        float h0 = fmaxf(c0 + bj.x, 0.f);
        float h1 = fmaxf(c1 + bj.y, 0.f);
        float h2 = fmaxf(c2 + bj.x, 0.f);
        float h3 = fmaxf(c3 + bj.y, 0.f);

        if (LAYER == 0) {
            int g0 = m0 + r0 + qr, g1 = g0 + 8;
            if (g0 < N_NODES)
                *(__half2*)(g_cat2 + (size_t)g0 * 128 + 64 + j0 + qc * 2) = __floats2half2_rn(h0, h1);
            if (g1 < N_NODES)
                *(__half2*)(g_cat2 + (size_t)g1 * 128 + 64 + j0 + qc * 2) = __floats2half2_rn(h2, h3);
        } else {
            float2 wa = *(const float2*)(Wlin + j0 + qc * 2);
            float2 wb = *(const float2*)(Wlin + 64 + j0 + qc * 2);
            pa0 += h0 * wa.x + h1 * wa.y;  pb0 += h0 * wb.x + h1 * wb.y;
            pa1 += h2 * wa.x + h3 * wa.y;  pb1 += h2 * wb.x + h3 * wb.y;
        }
    }

    if (LAYER == 1) {
        pa0 += __shfl_xor_sync(0xFFFFFFFFu, pa0, 1); pa0 += __shfl_xor_sync(0xFFFFFFFFu, pa0, 2);
        pb0 += __shfl_xor_sync(0xFFFFFFFFu, pb0, 1); pb0 += __shfl_xor_sync(0xFFFFFFFFu, pb0, 2);
        pa1 += __shfl_xor_sync(0xFFFFFFFFu, pa1, 1); pa1 += __shfl_xor_sync(0xFFFFFFFFu, pa1, 2);
        pb1 += __shfl_xor_sync(0xFFFFFFFFu, pb1, 1); pb1 += __shfl_xor_sync(0xFFFFFFFFu, pb1, 2);
        if (qc == 0) {
            int g0 = m0 + r0 + qr, g1 = g0 + 8;
            if (g0 < N_NODES) { g_sa[g0] = pa0; g_sb[g0] = pb0; }
            if (g1 < N_NODES) { g_sa[g1] = pa1; g_sb[g1] = pb1; }
        }
    }
}

// ---------------- final edge scores (4 edges per thread) ----------------
__global__ void edge_kernel(const int* __restrict__ ei,
                            const float* __restrict__ blin,
                            float* __restrict__ out)
{
    int e4 = blockIdx.x * blockDim.x + threadIdx.x;
    if (e4 >= N_EDGES / 4) return;
    int4 s = __ldg((const int4*)ei + e4);
    int4 d = __ldg((const int4*)(ei + N_EDGES) + e4);
    float b = __ldg(blin);
    float4 r;
    r.x = g_sa[s.x] + g_sb[d.x] + b;
    r.y = g_sa[s.y] + g_sb[d.y] + b;
    r.z = g_sa[s.z] + g_sb[d.z] + b;
    r.w = g_sa[s.w] + g_sb[d.w] + b;
    ((float4*)out)[e4] = r;
}

// ---------------- launch ----------------
extern "C" void kernel_launch(void* const* d_in, const int* in_sizes, int n_in,
                              void* d_out, int out_size)
{
    const float* x    = (const float*)d_in[0];
    const int*   ei   = (const int*)  d_in[1];
    const float* W1l  = (const float*)d_in[2];
    const float* b1l  = (const float*)d_in[3];
    const float* W1r  = (const float*)d_in[4];
    const float* W2l  = (const float*)d_in[5];
    const float* b2l  = (const float*)d_in[6];
    const float* W2r  = (const float*)d_in[7];
    const float* Wlin = (const float*)d_in[8];
    const float* blin = (const float*)d_in[9];
    float* out = (float*)d_out;

    const int E4B = (N_EDGES / 4 + 255) / 256;

    int* p_deg; cudaGetSymbolAddress((void**)&p_deg, g_deg);
    cudaMemsetAsync(p_deg, 0, N_NODES * sizeof(int), 0);   // memset node, not a kernel

    // fused pre-pass: hist atomics + x->fp16 + weight packing
    pre_kernel<<<HB + CB + WB, 256>>>(ei, x, W1l, W1r, W2l, W2r);

    scanA_kernel<<<NTILES, 1024>>>();
    scanB_kernel<<<1, 128>>>();
    scanC_kernel<<<NTILES, 1024>>>();
    fill_kernel<<<E4B, 256>>>(ei);

    // layer 1
    agg_kernel<0><<<N_NODES * 32 / 256, 256>>>();
    gemm_kernel<0><<<MTILES, 128>>>(b1l, nullptr);

    // layer 2 (h2 never materialized; sa/sb produced in epilogue)
    agg_kernel<1><<<N_NODES * 32 / 256, 256>>>();
    gemm_kernel<1><<<MTILES, 128>>>(b2l, Wlin);

    // edge scoring
    edge_kernel<<<E4B, 256>>>(ei, blin, out);
}

// round 12
// speedup vs baseline: 1.0252x; 1.0252x over previous
#include <cuda_runtime.h>
#include <cuda_fp16.h>

#define N_NODES 100000
#define N_EDGES 1600000
#define F 64
#define NTILES ((N_NODES + 1023) / 1024)   // 98
#define MTILES ((N_NODES + 63) / 64)       // 1563
#define PAD_E  2400000                     // 1.6M edges + <=700k padding
#define HB 1563                            // hist blocks
#define PB 2344                            // csr-prefill blocks (600000 uint4 / 256)
#define CB 1563                            // conv blocks
#define WB 64                              // wprep blocks

typedef unsigned long long ull;

// ---------------- scratch (static device globals; no allocation) ----------------
// NOTE: rows N_NODES of g_xh / g_cat2 are zero-initialized and never written:
// they serve as the gather target for padded CSR slots.
__device__ int    g_deg[N_NODES];
__device__ int    g_cursor[N_NODES];
__device__ int    g_row_ptr[N_NODES];          // padded offsets
__device__ int    g_csr_src[PAD_E];
__device__ int    g_tile_sum[NTILES];
__device__ __half g_xh[(size_t)(N_NODES + 1) * 64];     // fp16 x  (+ zero row)
__device__ __half g_mh1[(size_t)N_NODES * 64];          // fp16 mean1
__device__ __half g_cat2[(size_t)(N_NODES + 1) * 128];  // [mean2 | h1] (+ zero row)
__device__ __half g_w1[64 * 128];                        // [W1l | W1r] fp16
__device__ __half g_w2[64 * 128];
__device__ float  g_sa[N_NODES];
__device__ float  g_sb[N_NODES];

// fused cvt(half2->f32x2) + packed add: ~4 SASS instr, no predicates
__device__ __forceinline__ ull h2f_add(ull acc, unsigned h) {
    ull r;
    asm("{\n\t"
        ".reg .b16 lo, hi;\n\t"
        ".reg .f32 fl, fh;\n\t"
        ".reg .b64 v;\n\t"
        "mov.b32 {lo, hi}, %2;\n\t"
        "cvt.f32.f16 fl, lo;\n\t"
        "cvt.f32.f16 fh, hi;\n\t"
        "mov.b64 v, {fl, fh};\n\t"
        "add.rn.f32x2 %0, %1, v;\n\t"
        "}" : "=l"(r) : "l"(acc), "r"(h));
    return r;
}
__device__ __forceinline__ ull add2(ull a, ull b) {
    ull d; asm("add.rn.f32x2 %0, %1, %2;" : "=l"(d) : "l"(a), "l"(b)); return d;
}
__device__ __forceinline__ float2 unpack2(ull a) {
    float x, y; asm("mov.b64 {%0, %1}, %2;" : "=f"(x), "=f"(y) : "l"(a));
    return make_float2(x, y);
}

// ---------------- pre: hist + csr prefill + x->fp16 + weight pack (one launch) ----------------
__global__ void pre_kernel(const int* __restrict__ ei, const float* __restrict__ x,
                           const float* __restrict__ W1l, const float* __restrict__ W1r,
                           const float* __restrict__ W2l, const float* __restrict__ W2r)
{
    int b = blockIdx.x, t = threadIdx.x;
    if (b < HB) {                               // histogram of dst degrees
        int e4 = b * 256 + t;
        if (e4 >= N_EDGES / 4) return;
        int4 d = __ldg((const int4*)(ei + N_EDGES) + e4);
        atomicAdd(&g_deg[d.x], 1);
        atomicAdd(&g_deg[d.y], 1);
        atomicAdd(&g_deg[d.z], 1);
        atomicAdd(&g_deg[d.w], 1);
    } else if (b < HB + PB) {                   // prefill csr with zero-row index
        int i = (b - HB) * 256 + t;
        if (i < PAD_E / 4)
            ((int4*)g_csr_src)[i] = make_int4(N_NODES, N_NODES, N_NODES, N_NODES);
    } else if (b < HB + PB + CB) {              // x -> fp16
        int i = (b - HB - PB) * 256 + t;        // 16 floats per thread
        if (i >= N_NODES * F / 16) return;
        const float4* src = (const float4*)x + (size_t)i * 4;
        uint4 o0, o1;
        float4 v0 = __ldg(src);     float4 v1 = __ldg(src + 1);
        float4 v2 = __ldg(src + 2); float4 v3 = __ldg(src + 3);
        __half2 h;
        h = __floats2half2_rn(v0.x, v0.y); o0.x = *(unsigned*)&h;
        h = __floats2half2_rn(v0.z, v0.w); o0.y = *(unsigned*)&h;
        h = __floats2half2_rn(v1.x, v1.y); o0.z = *(unsigned*)&h;
        h = __floats2half2_rn(v1.z, v1.w); o0.w = *(unsigned*)&h;
        h = __floats2half2_rn(v2.x, v2.y); o1.x = *(unsigned*)&h;
        h = __floats2half2_rn(v2.z, v2.w); o1.y = *(unsigned*)&h;
        h = __floats2half2_rn(v3.x, v3.y); o1.z = *(unsigned*)&h;
        h = __floats2half2_rn(v3.z, v3.w); o1.w = *(unsigned*)&h;
        ((uint4*)g_xh)[(size_t)i * 2]     = o0;
        ((uint4*)g_xh)[(size_t)i * 2 + 1] = o1;
    } else {                                    // weight packing
        int i = (b - HB - PB - CB) * 256 + t;
        if (i >= 2 * 64 * 128) return;
        int sel = i >> 13;
        int r = i & 8191;
        int j = r >> 7, k = r & 127;
        const float* Wl = sel ? W2l : W1l;
        const float* Wr = sel ? W2r : W1r;
        float v = (k < 64) ? Wl[j * 64 + k] : Wr[j * 64 + (k - 64)];
        (sel ? g_w2 : g_w1)[r] = __float2half_rn(v);
    }
}

// ---------------- scans over PADDED degrees ----------------
__global__ void scanA_kernel() {
    __shared__ int wsum[32];
    int t = threadIdx.x, b = blockIdx.x;
    int i = b * 1024 + t;
    int v = (i < N_NODES) ? ((g_deg[i] + 7) & ~7) : 0;
#pragma unroll
    for (int off = 16; off; off >>= 1)
        v += __shfl_down_sync(0xFFFFFFFFu, v, off);
    if ((t & 31) == 0) wsum[t >> 5] = v;
    __syncthreads();
    if (t < 32) {
        int s = wsum[t];
#pragma unroll
        for (int off = 16; off; off >>= 1)
            s += __shfl_down_sync(0xFFFFFFFFu, s, off);
        if (t == 0) g_tile_sum[b] = s;
    }
}

// scanC': block scan + direct base computation (scanB folded in)
__global__ void scanC_kernel() {
    __shared__ int wsum[32];
    __shared__ int wbase;
    int t = threadIdx.x, b = blockIdx.x;
    int i = b * 1024 + t;
    int v = (i < N_NODES) ? ((g_deg[i] + 7) & ~7) : 0;
    int lane = t & 31, w = t >> 5;
    int x = v;
#pragma unroll
    for (int off = 1; off < 32; off <<= 1) {
        int y = __shfl_up_sync(0xFFFFFFFFu, x, off);
        if (lane >= off) x += y;
    }
    if (lane == 31) wsum[w] = x;
    __syncthreads();
    if (t < 32) {
        int s = wsum[t];
#pragma unroll
        for (int off = 1; off < 32; off <<= 1) {
            int y = __shfl_up_sync(0xFFFFFFFFu, s, off);
            if (t >= off) s += y;
        }
        wsum[t] = s;
        // base = sum of preceding tiles' sums (<= 97 values)
        int acc = 0;
        for (int j = t; j < b; j += 32) acc += g_tile_sum[j];
#pragma unroll
        for (int off = 16; off; off >>= 1)
            acc += __shfl_down_sync(0xFFFFFFFFu, acc, off);
        if (t == 0) wbase = acc;
    }
    __syncthreads();
    int base = wbase + (w ? wsum[w - 1] : 0);
    int excl = base + x - v;
    if (i < N_NODES) { g_row_ptr[i] = excl; g_cursor[i] = excl; }
}

__global__ void fill_kernel(const int* __restrict__ ei) {
    int e4 = blockIdx.x * blockDim.x + threadIdx.x;
    if (e4 >= N_EDGES / 4) return;
    int4 s = __ldg((const int4*)ei + e4);
    int4 d = __ldg((const int4*)(ei + N_EDGES) + e4);
    g_csr_src[atomicAdd(&g_cursor[d.x], 1)] = s.x;
    g_csr_src[atomicAdd(&g_cursor[d.y], 1)] = s.y;
    g_csr_src[atomicAdd(&g_cursor[d.z], 1)] = s.z;
    g_csr_src[atomicAdd(&g_cursor[d.w], 1)] = s.w;
}

// ---------------- mean aggregation: predicate-free padded CSR, fp16 gather ----------------
// Warp-per-node. Per 8 edges: 2 broadcast LDG.128 (idx) + 8 LDG.32 (half2 row)
// + 8 fused cvt+f32x2-add. Padded slots hit the zero row (index N_NODES).
template<int LAYER>
__global__ void agg_kernel() {
    int warp = (blockIdx.x * blockDim.x + threadIdx.x) >> 5;
    int lane = threadIdx.x & 31;
    if (warp >= N_NODES) return;

    const int beg  = g_row_ptr[warp];
    const int deg  = g_deg[warp];
    const int iters = (deg + 7) >> 3;
    const unsigned* __restrict__ xh = (const unsigned*)(LAYER == 0 ? g_xh : g_cat2);
    const int stride = (LAYER == 0) ? 32 : 64;
    const int off    = (LAYER == 0) ? 0  : 32;

    const int4* __restrict__ ip = (const int4*)(g_csr_src + beg);

    ull a0 = 0, a1 = 0, a2 = 0, a3 = 0;

    for (int it = 0; it < iters; it++) {
        int4 ia = __ldg(ip + 2 * it);
        int4 ib = __ldg(ip + 2 * it + 1);
        unsigned r0 = __ldg(xh + (size_t)ia.x * stride + off + lane);
        unsigned r1 = __ldg(xh + (size_t)ia.y * stride + off + lane);
        unsigned r2 = __ldg(xh + (size_t)ia.z * stride + off + lane);
        unsigned r3 = __ldg(xh + (size_t)ia.w * stride + off + lane);
        unsigned r4 = __ldg(xh + (size_t)ib.x * stride + off + lane);
        unsigned r5 = __ldg(xh + (size_t)ib.y * stride + off + lane);
        unsigned r6 = __ldg(xh + (size_t)ib.z * stride + off + lane);
        unsigned r7 = __ldg(xh + (size_t)ib.w * stride + off + lane);
        a0 = h2f_add(a0, r0);
        a1 = h2f_add(a1, r1);
        a2 = h2f_add(a2, r2);
        a3 = h2f_add(a3, r3);
        a0 = h2f_add(a0, r4);
        a1 = h2f_add(a1, r5);
        a2 = h2f_add(a2, r6);
        a3 = h2f_add(a3, r7);
    }

    float2 acc = unpack2(add2(add2(a0, a1), add2(a2, a3)));
    float inv = (deg > 0) ? 1.0f / (float)deg : 0.0f;
    __half2 r = __floats2half2_rn(acc.x * inv, acc.y * inv);
    if (LAYER == 0) ((__half2*)g_mh1)[(size_t)warp * 32 + lane] = r;
    else            ((__half2*)g_cat2)[(size_t)warp * 64 + lane] = r;
}

// ---------------- HMMA transform: out = relu([mean|x] @ [Wl|Wr]^T + b) ----------------
template<int LAYER>
__global__ void __launch_bounds__(128) gemm_kernel(
    const float* __restrict__ bias,
    const float* __restrict__ Wlin)
{
    __shared__ __half smA[64 * 136];   // 272B row stride: conflict-free quads
    const int m0 = blockIdx.x * 64;
    const int tid = threadIdx.x;
    const __half* __restrict__ W = (LAYER == 0) ? g_w1 : g_w2;

    if (LAYER == 0) {
#pragma unroll
        for (int i = 0; i < 4; i++) {   // left: mh1 rows
            int chunk = tid + i * 128;
            int r = chunk >> 3, c = chunk & 7;
            uint4 v = make_uint4(0, 0, 0, 0);
            if (m0 + r < N_NODES) v = *(const uint4*)(g_mh1 + (size_t)(m0 + r) * 64 + c * 8);
            *(uint4*)(smA + r * 136 + c * 8) = v;
        }
#pragma unroll
        for (int i = 0; i < 4; i++) {   // right: xh rows
            int chunk = tid + i * 128;
            int r = chunk >> 3, c = chunk & 7;
            uint4 v = make_uint4(0, 0, 0, 0);
            if (m0 + r < N_NODES) v = *(const uint4*)(g_xh + (size_t)(m0 + r) * 64 + c * 8);
            *(uint4*)(smA + r * 136 + 64 + c * 8) = v;
        }
    } else {
#pragma unroll
        for (int i = 0; i < 8; i++) {
            int chunk = tid + i * 128;
            int r = chunk >> 4, c = chunk & 15;
            uint4 v = make_uint4(0, 0, 0, 0);
            if (m0 + r < N_NODES) v = *(const uint4*)(g_cat2 + (size_t)(m0 + r) * 128 + c * 8);
            *(uint4*)(smA + r * 136 + c * 8) = v;
        }
    }
    __syncthreads();

    const int w = tid >> 5, lane = tid & 31;
    const int qr = lane >> 2, qc = lane & 3;
    const int r0 = w * 16;

    unsigned a[8][4];
#pragma unroll
    for (int k = 0; k < 8; k++) {
        const __half* base = smA + (r0 + qr) * 136 + k * 16 + qc * 2;
        a[k][0] = *(const unsigned*)(base);
        a[k][1] = *(const unsigned*)(base + 8 * 136);
        a[k][2] = *(const unsigned*)(base + 8);
        a[k][3] = *(const unsigned*)(base + 8 * 136 + 8);
    }

    float pa0 = 0.f, pb0 = 0.f, pa1 = 0.f, pb1 = 0.f;

#pragma unroll
    for (int nt = 0; nt < 8; nt++) {
        const int j0 = nt * 8;
        float c0 = 0.f, c1 = 0.f, c2 = 0.f, c3 = 0.f;
#pragma unroll
        for (int k = 0; k < 8; k++) {
            const __half* bb = W + (size_t)(j0 + qr) * 128 + k * 16 + qc * 2;
            unsigned b0 = __ldg((const unsigned*)bb);
            unsigned b1 = __ldg((const unsigned*)(bb + 8));
            asm volatile(
                "mma.sync.aligned.m16n8k16.row.col.f32.f16.f16.f32 "
                "{%0,%1,%2,%3}, {%4,%5,%6,%7}, {%8,%9}, {%0,%1,%2,%3};"
                : "+f"(c0), "+f"(c1), "+f"(c2), "+f"(c3)
                : "r"(a[k][0]), "r"(a[k][1]), "r"(a[k][2]), "r"(a[k][3]),
                  "r"(b0), "r"(b1));
        }
        float2 bj = *(const float2*)(bias + j0 + qc * 2);
        float h0 = fmaxf(c0 + bj.x, 0.f);
        float h1 = fmaxf(c1 + bj.y, 0.f);
        float h2 = fmaxf(c2 + bj.x, 0.f);
        float h3 = fmaxf(c3 + bj.y, 0.f);

        if (LAYER == 0) {
            int g0 = m0 + r0 + qr, g1 = g0 + 8;
            if (g0 < N_NODES)
                *(__half2*)(g_cat2 + (size_t)g0 * 128 + 64 + j0 + qc * 2) = __floats2half2_rn(h0, h1);
            if (g1 < N_NODES)
                *(__half2*)(g_cat2 + (size_t)g1 * 128 + 64 + j0 + qc * 2) = __floats2half2_rn(h2, h3);
        } else {
            float2 wa = *(const float2*)(Wlin + j0 + qc * 2);
            float2 wb = *(const float2*)(Wlin + 64 + j0 + qc * 2);
            pa0 += h0 * wa.x + h1 * wa.y;  pb0 += h0 * wb.x + h1 * wb.y;
            pa1 += h2 * wa.x + h3 * wa.y;  pb1 += h2 * wb.x + h3 * wb.y;
        }
    }

    if (LAYER == 1) {
        pa0 += __shfl_xor_sync(0xFFFFFFFFu, pa0, 1); pa0 += __shfl_xor_sync(0xFFFFFFFFu, pa0, 2);
        pb0 += __shfl_xor_sync(0xFFFFFFFFu, pb0, 1); pb0 += __shfl_xor_sync(0xFFFFFFFFu, pb0, 2);
        pa1 += __shfl_xor_sync(0xFFFFFFFFu, pa1, 1); pa1 += __shfl_xor_sync(0xFFFFFFFFu, pa1, 2);
        pb1 += __shfl_xor_sync(0xFFFFFFFFu, pb1, 1); pb1 += __shfl_xor_sync(0xFFFFFFFFu, pb1, 2);
        if (qc == 0) {
            int g0 = m0 + r0 + qr, g1 = g0 + 8;
            if (g0 < N_NODES) { g_sa[g0] = pa0; g_sb[g0] = pb0; }
            if (g1 < N_NODES) { g_sa[g1] = pa1; g_sb[g1] = pb1; }
        }
    }
}

// ---------------- final edge scores (4 edges per thread) ----------------
__global__ void edge_kernel(const int* __restrict__ ei,
                            const float* __restrict__ blin,
                            float* __restrict__ out)
{
    int e4 = blockIdx.x * blockDim.x + threadIdx.x;
    if (e4 >= N_EDGES / 4) return;
    int4 s = __ldg((const int4*)ei + e4);
    int4 d = __ldg((const int4*)(ei + N_EDGES) + e4);
    float b = __ldg(blin);
    float4 r;
    r.x = g_sa[s.x] + g_sb[d.x] + b;
    r.y = g_sa[s.y] + g_sb[d.y] + b;
    r.z = g_sa[s.z] + g_sb[d.z] + b;
    r.w = g_sa[s.w] + g_sb[d.w] + b;
    ((float4*)out)[e4] = r;
}

// ---------------- launch ----------------
extern "C" void kernel_launch(void* const* d_in, const int* in_sizes, int n_in,
                              void* d_out, int out_size)
{
    const float* x    = (const float*)d_in[0];
    const int*   ei   = (const int*)  d_in[1];
    const float* W1l  = (const float*)d_in[2];
    const float* b1l  = (const float*)d_in[3];
    const float* W1r  = (const float*)d_in[4];
    const float* W2l  = (const float*)d_in[5];
    const float* b2l  = (const float*)d_in[6];
    const float* W2r  = (const float*)d_in[7];
    const float* Wlin = (const float*)d_in[8];
    const float* blin = (const float*)d_in[9];
    float* out = (float*)d_out;

    const int E4B = (N_EDGES / 4 + 255) / 256;

    int* p_deg; cudaGetSymbolAddress((void**)&p_deg, g_deg);
    cudaMemsetAsync(p_deg, 0, N_NODES * sizeof(int), 0);   // memset node, not a kernel

    // fused pre-pass: hist + csr prefill + x->fp16 + weight packing
    pre_kernel<<<HB + PB + CB + WB, 256>>>(ei, x, W1l, W1r, W2l, W2r);

    scanA_kernel<<<NTILES, 1024>>>();
    scanC_kernel<<<NTILES, 1024>>>();
    fill_kernel<<<E4B, 256>>>(ei);

    // layer 1
    agg_kernel<0><<<N_NODES * 32 / 256, 256>>>();
    gemm_kernel<0><<<MTILES, 128>>>(b1l, nullptr);

    // layer 2 (h2 never materialized; sa/sb produced in epilogue)
    agg_kernel<1><<<N_NODES * 32 / 256, 256>>>();
    gemm_kernel<1><<<MTILES, 128>>>(b2l, Wlin);

    // edge scoring
    edge_kernel<<<E4B, 256>>>(ei, blin, out);
}

// round 14
// speedup vs baseline: 1.0449x; 1.0192x over previous
#include <cuda_runtime.h>
#include <cuda_fp16.h>

#define N_NODES 100000
#define N_EDGES 1600000
#define F 64
#define NTILES ((N_NODES + 1023) / 1024)   // 98
#define MTILES ((N_NODES + 63) / 64)       // 1563
#define PAD_E  2400000                     // 1.6M edges + <=700k padding
#define HB 1563                            // hist blocks
#define PB 2344                            // csr-prefill blocks
#define CB 1563                            // conv blocks
#define WB 64                              // wprep blocks

typedef unsigned long long ull;

#if defined(__CUDA_ARCH__) && (__CUDA_ARCH__ >= 900)
#define PDL_SYNC() cudaGridDependencySynchronize()
#else
#define PDL_SYNC()
#endif

// ---------------- scratch (static device globals; no allocation) ----------------
// rows N_NODES of g_xh / g_cat2 are zero-initialized and never written:
// gather target for padded CSR slots.
__device__ int    g_deg[N_NODES];
__device__ int    g_cursor[N_NODES];
__device__ int    g_row_ptr[N_NODES];
__device__ int    g_csr_src[PAD_E];
__device__ int    g_tile_post[NTILES];     // published tile sums + 1 (0 = not ready)
__device__ __half g_xh[(size_t)(N_NODES + 1) * 64];     // fp16 x  (+ zero row)
__device__ __half g_mh1[(size_t)N_NODES * 64];          // fp16 mean1
__device__ __half g_cat2[(size_t)(N_NODES + 1) * 128];  // [mean2 | h1] (+ zero row)
__device__ __half g_w1[64 * 128];                        // [W1l | W1r] fp16
__device__ __half g_w2[64 * 128];
__device__ float  g_sa[N_NODES];
__device__ float  g_sb[N_NODES];

// fused cvt(half2->f32x2) + packed add
__device__ __forceinline__ ull h2f_add(ull acc, unsigned h) {
    ull r;
    asm("{\n\t"
        ".reg .b16 lo, hi;\n\t"
        ".reg .f32 fl, fh;\n\t"
        ".reg .b64 v;\n\t"
        "mov.b32 {lo, hi}, %2;\n\t"
        "cvt.f32.f16 fl, lo;\n\t"
        "cvt.f32.f16 fh, hi;\n\t"
        "mov.b64 v, {fl, fh};\n\t"
        "add.rn.f32x2 %0, %1, v;\n\t"
        "}" : "=l"(r) : "l"(acc), "r"(h));
    return r;
}
__device__ __forceinline__ ull add2(ull a, ull b) {
    ull d; asm("add.rn.f32x2 %0, %1, %2;" : "=l"(d) : "l"(a), "l"(b)); return d;
}
__device__ __forceinline__ float2 unpack2(ull a) {
    float x, y; asm("mov.b64 {%0, %1}, %2;" : "=f"(x), "=f"(y) : "l"(a));
    return make_float2(x, y);
}

// ---------------- pre: hist + csr prefill + x->fp16 + weight pack (one launch) ----------------
__global__ void pre_kernel(const int* __restrict__ ei, const float* __restrict__ x,
                           const float* __restrict__ W1l, const float* __restrict__ W1r,
                           const float* __restrict__ W2l, const float* __restrict__ W2r)
{
    PDL_SYNC();
    int b = blockIdx.x, t = threadIdx.x;
    if (b < HB) {                               // histogram of dst degrees
        int e4 = b * 256 + t;
        if (e4 >= N_EDGES / 4) return;
        int4 d = __ldg((const int4*)(ei + N_EDGES) + e4);
        atomicAdd(&g_deg[d.x], 1);
        atomicAdd(&g_deg[d.y], 1);
        atomicAdd(&g_deg[d.z], 1);
        atomicAdd(&g_deg[d.w], 1);
    } else if (b < HB + PB) {                   // prefill csr with zero-row index
        int i = (b - HB) * 256 + t;
        if (i < PAD_E / 4)
            ((int4*)g_csr_src)[i] = make_int4(N_NODES, N_NODES, N_NODES, N_NODES);
    } else if (b < HB + PB + CB) {              // x -> fp16
        int i = (b - HB - PB) * 256 + t;        // 16 floats per thread
        if (i >= N_NODES * F / 16) return;
        const float4* src = (const float4*)x + (size_t)i * 4;
        uint4 o0, o1;
        float4 v0 = __ldg(src);     float4 v1 = __ldg(src + 1);
        float4 v2 = __ldg(src + 2); float4 v3 = __ldg(src + 3);
        __half2 h;
        h = __floats2half2_rn(v0.x, v0.y); o0.x = *(unsigned*)&h;
        h = __floats2half2_rn(v0.z, v0.w); o0.y = *(unsigned*)&h;
        h = __floats2half2_rn(v1.x, v1.y); o0.z = *(unsigned*)&h;
        h = __floats2half2_rn(v1.z, v1.w); o0.w = *(unsigned*)&h;
        h = __floats2half2_rn(v2.x, v2.y); o1.x = *(unsigned*)&h;
        h = __floats2half2_rn(v2.z, v2.w); o1.y = *(unsigned*)&h;
        h = __floats2half2_rn(v3.x, v3.y); o1.z = *(unsigned*)&h;
        h = __floats2half2_rn(v3.z, v3.w); o1.w = *(unsigned*)&h;
        ((uint4*)g_xh)[(size_t)i * 2]     = o0;
        ((uint4*)g_xh)[(size_t)i * 2 + 1] = o1;
    } else {                                    // weight packing
        int i = (b - HB - PB - CB) * 256 + t;
        if (i >= 2 * 64 * 128) return;
        int sel = i >> 13;
        int r = i & 8191;
        int j = r >> 7, k = r & 127;
        const float* Wl = sel ? W2l : W1l;
        const float* Wr = sel ? W2r : W1r;
        float v = (k < 64) ? Wl[j * 64 + k] : Wr[j * 64 + (k - 64)];
        (sel ? g_w2 : g_w1)[r] = __float2half_rn(v);
    }
}

// ---------------- merged scan: padded degrees -> row_ptr/cursor, single launch ----------------
// 98 blocks < 148 SMs: whole grid is one wave, so cross-block spin is safe.
__global__ void scan_kernel() {
    PDL_SYNC();
    __shared__ int wsum[32];
    __shared__ int sbase;
    int t = threadIdx.x, b = blockIdx.x;
    int i = b * 1024 + t;
    int v = (i < N_NODES) ? ((g_deg[i] + 7) & ~7) : 0;
    int lane = t & 31, w = t >> 5;
    int x = v;
#pragma unroll
    for (int off = 1; off < 32; off <<= 1) {
        int y = __shfl_up_sync(0xFFFFFFFFu, x, off);
        if (lane >= off) x += y;
    }
    if (lane == 31) wsum[w] = x;
    __syncthreads();
    if (t < 32) {
        int s = wsum[t];
#pragma unroll
        for (int off = 1; off < 32; off <<= 1) {
            int y = __shfl_up_sync(0xFFFFFFFFu, s, off);
            if (t >= off) s += y;
        }
        wsum[t] = s;
        if (t == 31) {            // publish this tile's total (+1 sentinel)
            __threadfence();
            atomicExch(&g_tile_post[b], s + 1);
        }
    }
    __syncthreads();
    if (t < 32) {                 // lookback over preceding tiles
        int acc = 0;
        for (int j = t; j < b; j += 32) {
            int p;
            do { p = atomicAdd(&g_tile_post[j], 0); } while (p == 0);
            acc += p - 1;
        }
#pragma unroll
        for (int off = 16; off; off >>= 1)
            acc += __shfl_down_sync(0xFFFFFFFFu, acc, off);
        if (t == 0) sbase = acc;
    }
    __syncthreads();
    int base = sbase + (w ? wsum[w - 1] : 0);
    int excl = base + x - v;
    if (i < N_NODES) { g_row_ptr[i] = excl; g_cursor[i] = excl; }
}

__global__ void fill_kernel(const int* __restrict__ ei) {
    PDL_SYNC();
    int e4 = blockIdx.x * blockDim.x + threadIdx.x;
    if (e4 >= N_EDGES / 4) return;
    int4 s = __ldg((const int4*)ei + e4);
    int4 d = __ldg((const int4*)(ei + N_EDGES) + e4);
    g_csr_src[atomicAdd(&g_cursor[d.x], 1)] = s.x;
    g_csr_src[atomicAdd(&g_cursor[d.y], 1)] = s.y;
    g_csr_src[atomicAdd(&g_cursor[d.z], 1)] = s.z;
    g_csr_src[atomicAdd(&g_cursor[d.w], 1)] = s.w;
}

// ---------------- mean aggregation: predicate-free padded CSR, fp16 gather ----------------
template<int LAYER>
__global__ void agg_kernel() {
    PDL_SYNC();
    int warp = (blockIdx.x * blockDim.x + threadIdx.x) >> 5;
    int lane = threadIdx.x & 31;
    if (warp >= N_NODES) return;

    const int beg  = g_row_ptr[warp];
    const int deg  = g_deg[warp];
    const int iters = (deg + 7) >> 3;
    const unsigned* __restrict__ xh = (const unsigned*)(LAYER == 0 ? g_xh : g_cat2);
    const int stride = (LAYER == 0) ? 32 : 64;
    const int off    = (LAYER == 0) ? 0  : 32;

    const int4* __restrict__ ip = (const int4*)(g_csr_src + beg);

    ull a0 = 0, a1 = 0, a2 = 0, a3 = 0;

    for (int it = 0; it < iters; it++) {
        int4 ia = __ldg(ip + 2 * it);
        int4 ib = __ldg(ip + 2 * it + 1);
        unsigned r0 = __ldg(xh + (size_t)ia.x * stride + off + lane);
        unsigned r1 = __ldg(xh + (size_t)ia.y * stride + off + lane);
        unsigned r2 = __ldg(xh + (size_t)ia.z * stride + off + lane);
        unsigned r3 = __ldg(xh + (size_t)ia.w * stride + off + lane);
        unsigned r4 = __ldg(xh + (size_t)ib.x * stride + off + lane);
        unsigned r5 = __ldg(xh + (size_t)ib.y * stride + off + lane);
        unsigned r6 = __ldg(xh + (size_t)ib.z * stride + off + lane);
        unsigned r7 = __ldg(xh + (size_t)ib.w * stride + off + lane);
        a0 = h2f_add(a0, r0);
        a1 = h2f_add(a1, r1);
        a2 = h2f_add(a2, r2);
        a3 = h2f_add(a3, r3);
        a0 = h2f_add(a0, r4);
        a1 = h2f_add(a1, r5);
        a2 = h2f_add(a2, r6);
        a3 = h2f_add(a3, r7);
    }

    float2 acc = unpack2(add2(add2(a0, a1), add2(a2, a3)));
    float inv = (deg > 0) ? 1.0f / (float)deg : 0.0f;
    __half2 r = __floats2half2_rn(acc.x * inv, acc.y * inv);
    if (LAYER == 0) ((__half2*)g_mh1)[(size_t)warp * 32 + lane] = r;
    else            ((__half2*)g_cat2)[(size_t)warp * 64 + lane] = r;
}

// ---------------- HMMA transform: out = relu([mean|x] @ [Wl|Wr]^T + b) ----------------
template<int LAYER>
__global__ void __launch_bounds__(128) gemm_kernel(
    const float* __restrict__ bias,
    const float* __restrict__ Wlin)
{
    PDL_SYNC();
    __shared__ __half smA[64 * 136];   // 272B row stride: conflict-free quads
    const int m0 = blockIdx.x * 64;
    const int tid = threadIdx.x;
    const __half* __restrict__ W = (LAYER == 0) ? g_w1 : g_w2;

    if (LAYER == 0) {
#pragma unroll
        for (int i = 0; i < 4; i++) {   // left: mh1 rows
            int chunk = tid + i * 128;
            int r = chunk >> 3, c = chunk & 7;
            uint4 v = make_uint4(0, 0, 0, 0);
            if (m0 + r < N_NODES) v = *(const uint4*)(g_mh1 + (size_t)(m0 + r) * 64 + c * 8);
            *(uint4*)(smA + r * 136 + c * 8) = v;
        }
#pragma unroll
        for (int i = 0; i < 4; i++) {   // right: xh rows
            int chunk = tid + i * 128;
            int r = chunk >> 3, c = chunk & 7;
            uint4 v = make_uint4(0, 0, 0, 0);
            if (m0 + r < N_NODES) v = *(const uint4*)(g_xh + (size_t)(m0 + r) * 64 + c * 8);
            *(uint4*)(smA + r * 136 + 64 + c * 8) = v;
        }
    } else {
#pragma unroll
        for (int i = 0; i < 8; i++) {
            int chunk = tid + i * 128;
            int r = chunk >> 4, c = chunk & 15;
            uint4 v = make_uint4(0, 0, 0, 0);
            if (m0 + r < N_NODES) v = *(const uint4*)(g_cat2 + (size_t)(m0 + r) * 128 + c * 8);
            *(uint4*)(smA + r * 136 + c * 8) = v;
        }
    }
    __syncthreads();

    const int w = tid >> 5, lane = tid & 31;
    const int qr = lane >> 2, qc = lane & 3;
    const int r0 = w * 16;

    unsigned a[8][4];
#pragma unroll
    for (int k = 0; k < 8; k++) {
        const __half* base = smA + (r0 + qr) * 136 + k * 16 + qc * 2;
        a[k][0] = *(const unsigned*)(base);
        a[k][1] = *(const unsigned*)(base + 8 * 136);
        a[k][2] = *(const unsigned*)(base + 8);
        a[k][3] = *(const unsigned*)(base + 8 * 136 + 8);
    }

    float pa0 = 0.f, pb0 = 0.f, pa1 = 0.f, pb1 = 0.f;

#pragma unroll
    for (int nt = 0; nt < 8; nt++) {
        const int j0 = nt * 8;
        float c0 = 0.f, c1 = 0.f, c2 = 0.f, c3 = 0.f;
#pragma unroll
        for (int k = 0; k < 8; k++) {
            const __half* bb = W + (size_t)(j0 + qr) * 128 + k * 16 + qc * 2;
            unsigned b0 = __ldg((const unsigned*)bb);
            unsigned b1 = __ldg((const unsigned*)(bb + 8));
            asm volatile(
                "mma.sync.aligned.m16n8k16.row.col.f32.f16.f16.f32 "
                "{%0,%1,%2,%3}, {%4,%5,%6,%7}, {%8,%9}, {%0,%1,%2,%3};"
                : "+f"(c0), "+f"(c1), "+f"(c2), "+f"(c3)
                : "r"(a[k][0]), "r"(a[k][1]), "r"(a[k][2]), "r"(a[k][3]),
                  "r"(b0), "r"(b1));
        }
        float2 bj = *(const float2*)(bias + j0 + qc * 2);
        float h0 = fmaxf(c0 + bj.x, 0.f);
        float h1 = fmaxf(c1 + bj.y, 0.f);
        float h2 = fmaxf(c2 + bj.x, 0.f);
        float h3 = fmaxf(c3 + bj.y, 0.f);

        if (LAYER == 0) {
            int g0 = m0 + r0 + qr, g1 = g0 + 8;
            if (g0 < N_NODES)
                *(__half2*)(g_cat2 + (size_t)g0 * 128 + 64 + j0 + qc * 2) = __floats2half2_rn(h0, h1);
            if (g1 < N_NODES)
                *(__half2*)(g_cat2 + (size_t)g1 * 128 + 64 + j0 + qc * 2) = __floats2half2_rn(h2, h3);
        } else {
            float2 wa = *(const float2*)(Wlin + j0 + qc * 2);
            float2 wb = *(const float2*)(Wlin + 64 + j0 + qc * 2);
            pa0 += h0 * wa.x + h1 * wa.y;  pb0 += h0 * wb.x + h1 * wb.y;
            pa1 += h2 * wa.x + h3 * wa.y;  pb1 += h2 * wb.x + h3 * wb.y;
        }
    }

    if (LAYER == 1) {
        pa0 += __shfl_xor_sync(0xFFFFFFFFu, pa0, 1); pa0 += __shfl_xor_sync(0xFFFFFFFFu, pa0, 2);
        pb0 += __shfl_xor_sync(0xFFFFFFFFu, pb0, 1); pb0 += __shfl_xor_sync(0xFFFFFFFFu, pb0, 2);
        pa1 += __shfl_xor_sync(0xFFFFFFFFu, pa1, 1); pa1 += __shfl_xor_sync(0xFFFFFFFFu, pa1, 2);
        pb1 += __shfl_xor_sync(0xFFFFFFFFu, pb1, 1); pb1 += __shfl_xor_sync(0xFFFFFFFFu, pb1, 2);
        if (qc == 0) {
            int g0 = m0 + r0 + qr, g1 = g0 + 8;
            if (g0 < N_NODES) { g_sa[g0] = pa0; g_sb[g0] = pb0; }
            if (g1 < N_NODES) { g_sa[g1] = pa1; g_sb[g1] = pb1; }
        }
    }
}

// ---------------- final edge scores (4 edges per thread) ----------------
__global__ void edge_kernel(const int* __restrict__ ei,
                            const float* __restrict__ blin,
                            float* __restrict__ out)
{
    PDL_SYNC();
    int e4 = blockIdx.x * blockDim.x + threadIdx.x;
    if (e4 >= N_EDGES / 4) return;
    int4 s = __ldg((const int4*)ei + e4);
    int4 d = __ldg((const int4*)(ei + N_EDGES) + e4);
    float b = __ldg(blin);
    float4 r;
    r.x = g_sa[s.x] + g_sb[d.x] + b;
    r.y = g_sa[s.y] + g_sb[d.y] + b;
    r.z = g_sa[s.z] + g_sb[d.z] + b;
    r.w = g_sa[s.w] + g_sb[d.w] + b;
    ((float4*)out)[e4] = r;
}

// ---------------- PDL launch helper ----------------
static inline void pdl_launch(const void* fn, int grid, int block, void** args) {
    cudaLaunchConfig_t cfg = {};
    cfg.gridDim = dim3(grid, 1, 1);
    cfg.blockDim = dim3(block, 1, 1);
    cfg.dynamicSmemBytes = 0;
    cfg.stream = 0;
    cudaLaunchAttribute attr;
    attr.id = cudaLaunchAttributeProgrammaticStreamSerialization;
    attr.val.programmaticStreamSerializationAllowed = 1;
    cfg.attrs = &attr;
    cfg.numAttrs = 1;
    cudaLaunchKernelExC(&cfg, fn, args);
}

// ---------------- launch ----------------
extern "C" void kernel_launch(void* const* d_in, const int* in_sizes, int n_in,
                              void* d_out, int out_size)
{
    const float* x    = (const float*)d_in[0];
    const int*   ei   = (const int*)  d_in[1];
    const float* W1l  = (const float*)d_in[2];
    const float* b1l  = (const float*)d_in[3];
    const float* W1r  = (const float*)d_in[4];
    const float* W2l  = (const float*)d_in[5];
    const float* b2l  = (const float*)d_in[6];
    const float* W2r  = (const float*)d_in[7];
    const float* Wlin = (const float*)d_in[8];
    const float* blin = (const float*)d_in[9];
    float* out = (float*)d_out;

    const int E4B = (N_EDGES / 4 + 255) / 256;
    const int AGB = N_NODES * 32 / 256;

    int* p_deg;  cudaGetSymbolAddress((void**)&p_deg,  g_deg);
    int* p_post; cudaGetSymbolAddress((void**)&p_post, g_tile_post);

    // memset nodes (not kernel launches)
    cudaMemsetAsync(p_deg,  0, N_NODES * sizeof(int), 0);
    cudaMemsetAsync(p_post, 0, NTILES * sizeof(int), 0);

    {   // pre: hist + csr prefill + x->fp16 + weight packing
        void* a[] = {(void*)&ei, (void*)&x, (void*)&W1l, (void*)&W1r, (void*)&W2l, (void*)&W2r};
        pdl_launch((const void*)pre_kernel, HB + PB + CB + WB, 256, a);
    }
    {   // merged single-wave scan
        void* a[] = {nullptr};
        pdl_launch((const void*)scan_kernel, NTILES, 1024, a);
    }
    {   // CSR fill
        void* a[] = {(void*)&ei};
        pdl_launch((const void*)fill_kernel, E4B, 256, a);
    }
    {   // layer-1 aggregation
        void* a[] = {nullptr};
        pdl_launch((const void*)agg_kernel<0>, AGB, 256, a);
    }
    {   // layer-1 transform
        void* a[] = {(void*)&b1l, (void*)&Wlin};
        pdl_launch((const void*)gemm_kernel<0>, MTILES, 128, a);
    }
    {   // layer-2 aggregation
        void* a[] = {nullptr};
        pdl_launch((const void*)agg_kernel<1>, AGB, 256, a);
    }
    {   // layer-2 transform + fused edge-scorer halves
        void* a[] = {(void*)&b2l, (void*)&Wlin};
        pdl_launch((const void*)gemm_kernel<1>, MTILES, 128, a);
    }
    {   // edge scoring
        void* a[] = {(void*)&ei, (void*)&blin, (void*)&out};
        pdl_launch((const void*)edge_kernel, E4B, 256, a);
    }
}